// round 3
// baseline (speedup 1.0000x reference)
#include <cuda_runtime.h>
#include <cuda.h>
#include <cuda_bf16.h>
#include <cstdint>

// TopDownProjector via TMA gather.
// Volume viewed as 2D [n_cols, D] row-major fp32. TMA box {TOPK, CPB} pulls the
// top TOPK voxels (32B) of CPB columns into smem in one bulk-tensor op per
// block, bypassing the L1tex wavefront bottleneck of a scattered LDG gather.
// p(column unresolved by top 8) = (1/9)^8 ~ 2.3e-8 -> global-scan fallback.

static constexpr int D       = 256;
static constexpr int TOPK    = 8;     // 8 fp32 = 32B per column (TMA box0 min)
static constexpr int CPB     = 256;   // columns per block (TMA box1 max)
static constexpr int THREADS = 256;

__global__ void __launch_bounds__(THREADS)
topdown_tma_kernel(const __grid_constant__ CUtensorMap tmap,
                   const float* __restrict__ volume,
                   float* __restrict__ height,
                   float* __restrict__ seg,
                   int n_cols) {
    __shared__ alignas(128) float tile[CPB * TOPK];   // [CPB][TOPK]
    __shared__ alignas(8) uint64_t mbar;

    const int tid = threadIdx.x;
    const int col_base = blockIdx.x * CPB;

    uint32_t mbar_a = (uint32_t)__cvta_generic_to_shared(&mbar);
    uint32_t tile_a = (uint32_t)__cvta_generic_to_shared(tile);

    if (tid == 0) {
        asm volatile("mbarrier.init.shared.b64 [%0], 1;" :: "r"(mbar_a) : "memory");
        asm volatile("fence.proxy.async.shared::cta;" ::: "memory");
        asm volatile("mbarrier.arrive.expect_tx.shared.b64 _, [%0], %1;"
                     :: "r"(mbar_a), "r"((uint32_t)(CPB * TOPK * 4)) : "memory");
        asm volatile(
            "cp.async.bulk.tensor.2d.shared::cta.global.tile.mbarrier::complete_tx::bytes"
            " [%0], [%1, {%2, %3}], [%4];"
            :: "r"(tile_a), "l"(&tmap),
               "r"((int)(D - TOPK)), "r"(col_base), "r"(mbar_a)
            : "memory");
    }
    __syncthreads();

    // Wait for TMA completion (phase 0).
    asm volatile(
        "{\n\t.reg .pred P;\n\t"
        "WAIT_%=:\n\t"
        "mbarrier.try_wait.parity.acquire.cta.shared::cta.b64 P, [%0], 0;\n\t"
        "@!P bra WAIT_%=;\n\t}"
        :: "r"(mbar_a) : "memory");

    const int c = col_base + tid;
    if (c >= n_cols) return;

    const float* tp = tile + tid * TOPK;   // depths [D-TOPK, D)
    float4 hi = reinterpret_cast<const float4*>(tp)[1];  // 252..255
    float4 lo = reinterpret_cast<const float4*>(tp)[0];  // 248..251

    float hit_idx = 0.0f, hit_val = 0.0f;
    bool found = true;
    if      (hi.w != 0.0f) { hit_idx = (float)(D - 1); hit_val = hi.w; }
    else if (hi.z != 0.0f) { hit_idx = (float)(D - 2); hit_val = hi.z; }
    else if (hi.y != 0.0f) { hit_idx = (float)(D - 3); hit_val = hi.y; }
    else if (hi.x != 0.0f) { hit_idx = (float)(D - 4); hit_val = hi.x; }
    else if (lo.w != 0.0f) { hit_idx = (float)(D - 5); hit_val = lo.w; }
    else if (lo.z != 0.0f) { hit_idx = (float)(D - 6); hit_val = lo.z; }
    else if (lo.y != 0.0f) { hit_idx = (float)(D - 7); hit_val = lo.y; }
    else if (lo.x != 0.0f) { hit_idx = (float)(D - 8); hit_val = lo.x; }
    else found = false;

    if (!found) {   // ~2e-8 per column: scan the rest from global
        const float* colp = volume + (size_t)c * D;
        for (int k = D - TOPK - 1; k >= 0; --k) {
            float v = __ldg(colp + k);
            if (v != 0.0f) { hit_idx = (float)k; hit_val = v; break; }
        }
    }

    height[c] = hit_idx;
    seg[c]    = hit_val;
}

// ---------------- fallback path (no driver entry point) ----------------

__device__ __forceinline__ float2 resolve_col(const float* __restrict__ colp,
                                              float4 v) {
    int base = D - 4;
    for (;;) {
        if (v.w != 0.0f) return make_float2((float)(base + 3), v.w);
        if (v.z != 0.0f) return make_float2((float)(base + 2), v.z);
        if (v.y != 0.0f) return make_float2((float)(base + 1), v.y);
        if (v.x != 0.0f) return make_float2((float)(base + 0), v.x);
        base -= 4;
        if (base < 0) return make_float2(0.0f, 0.0f);
        v = *reinterpret_cast<const float4*>(colp + base);
    }
}

__global__ void topdown_kernel4(const float* __restrict__ volume,
                                float4* __restrict__ height4,
                                float4* __restrict__ seg4,
                                int n_quads) {
    int q = blockIdx.x * blockDim.x + threadIdx.x;
    if (q >= n_quads) return;
    const float* p0 = volume + ((size_t)q * 4 + 0) * D;
    const float* p1 = volume + ((size_t)q * 4 + 1) * D;
    const float* p2 = volume + ((size_t)q * 4 + 2) * D;
    const float* p3 = volume + ((size_t)q * 4 + 3) * D;
    float4 v0 = *reinterpret_cast<const float4*>(p0 + (D - 4));
    float4 v1 = *reinterpret_cast<const float4*>(p1 + (D - 4));
    float4 v2 = *reinterpret_cast<const float4*>(p2 + (D - 4));
    float4 v3 = *reinterpret_cast<const float4*>(p3 + (D - 4));
    float2 r0 = resolve_col(p0, v0);
    float2 r1 = resolve_col(p1, v1);
    float2 r2 = resolve_col(p2, v2);
    float2 r3 = resolve_col(p3, v3);
    height4[q] = make_float4(r0.x, r1.x, r2.x, r3.x);
    seg4[q]    = make_float4(r0.y, r1.y, r2.y, r3.y);
}

// ---------------- launch ----------------

typedef CUresult (*EncodeTiledFn)(
    CUtensorMap*, CUtensorMapDataType, cuuint32_t, void*,
    const cuuint64_t*, const cuuint64_t*, const cuuint32_t*, const cuuint32_t*,
    CUtensorMapInterleave, CUtensorMapSwizzle, CUtensorMapL2promotion,
    CUtensorMapFloatOOBfill);

extern "C" void kernel_launch(void* const* d_in, const int* in_sizes, int n_in,
                              void* d_out, int out_size) {
    const float* volume = (const float*)d_in[0];
    float* out = (float*)d_out;

    int n_cols = in_sizes[0] / D;      // 524288
    float* height = out;
    float* seg    = out + n_cols;

    // Resolve cuTensorMapEncodeTiled through cudart (no -lcuda needed).
    void* sym = nullptr;
    cudaDriverEntryPointQueryResult qr = cudaDriverEntryPointSymbolNotFound;
    bool tma_ok = false;
    if (cudaGetDriverEntryPoint("cuTensorMapEncodeTiled", &sym,
                                cudaEnableDefault, &qr) == cudaSuccess &&
        qr == cudaDriverEntryPointSuccess && sym != nullptr) {
        EncodeTiledFn encode = reinterpret_cast<EncodeTiledFn>(sym);
        CUtensorMap tmap;
        cuuint64_t dims[2]    = {(cuuint64_t)D, (cuuint64_t)n_cols};
        cuuint64_t strides[1] = {(cuuint64_t)D * sizeof(float)};
        cuuint32_t box[2]     = {(cuuint32_t)TOPK, (cuuint32_t)CPB};
        cuuint32_t estr[2]    = {1, 1};
        CUresult r = encode(&tmap, CU_TENSOR_MAP_DATA_TYPE_FLOAT32, 2,
                            (void*)volume, dims, strides, box, estr,
                            CU_TENSOR_MAP_INTERLEAVE_NONE,
                            CU_TENSOR_MAP_SWIZZLE_NONE,
                            CU_TENSOR_MAP_L2_PROMOTION_NONE,
                            CU_TENSOR_MAP_FLOAT_OOB_FILL_NONE);
        if (r == CUDA_SUCCESS) {
            int blocks = (n_cols + CPB - 1) / CPB;   // 2048
            topdown_tma_kernel<<<blocks, THREADS>>>(tmap, volume, height, seg,
                                                    n_cols);
            tma_ok = true;
        }
    }

    if (!tma_ok) {
        int n_quads = n_cols / 4;
        int threads = 256;
        int blocks = (n_quads + threads - 1) / threads;
        topdown_kernel4<<<blocks, threads>>>(volume, (float4*)height,
                                             (float4*)seg, n_quads);
    }
}